// round 13
// baseline (speedup 1.0000x reference)
#include <cuda_runtime.h>
#include <cuda_bf16.h>
#include <cstdint>

#define BATCH 2048
#define TLEN  200
#define HD    128
#define NA0   64
#define NA1   16
#define NB    16
#define RBLK  (BATCH / NB)   // 128 scan blocks
#define NR    384            // 3*HD gate rows
#define SG2P  386            // sg2 pitch (floats), even
#define APITCH 136           // bf16 A pitch: 272B rows -> conflict-free ldmatrix

// ---------------- device scratch (no allocs allowed) ----------------
__device__ float g_att[BATCH * TLEN];            // 1.6 MB attention scores
__device__ float g_qp [BATCH * NA0];             // 0.5 MB qpart
__device__ float g_gi [BATCH * TLEN * NR];       // 629 MB  gi = keys@Wih^T + bih
__device__ uint2 g_wfhi[48 * 8 * 32];            // Wih hi fragments (98KB)
__device__ uint2 g_wflo[48 * 8 * 32];            // Wih lo fragments (98KB)

// ---------------- helpers ----------------
__device__ __forceinline__ unsigned long long ffma2(unsigned long long a,
                                                    unsigned long long b,
                                                    unsigned long long c) {
    unsigned long long d;
    asm("fma.rn.f32x2 %0, %1, %2, %3;" : "=l"(d) : "l"(a), "l"(b), "l"(c));
    return d;
}
__device__ __forceinline__ float2 unpk(unsigned long long v) {
    float2 f;
    asm("mov.b64 {%0, %1}, %2;" : "=f"(f.x), "=f"(f.y) : "l"(v));
    return f;
}
__device__ __forceinline__ float sigm(float x) {
    return __fdividef(1.0f, 1.0f + __expf(-x));
}
__device__ __forceinline__ float tanh_fast(float x) {
    float y;
    asm("tanh.approx.f32 %0, %1;" : "=f"(y) : "f"(x));
    return y;
}
__device__ __forceinline__ float sigm_t(float x) {
    return fmaf(0.5f, tanh_fast(0.5f * x), 0.5f);
}
__device__ __forceinline__ uint32_t pkbf(float lo, float hi) {
    __nv_bfloat16 a = __float2bfloat16(lo), b = __float2bfloat16(hi);
    uint16_t ua = *reinterpret_cast<uint16_t*>(&a);
    uint16_t ub = *reinterpret_cast<uint16_t*>(&b);
    return (uint32_t)ua | ((uint32_t)ub << 16);
}
__device__ __forceinline__ void mma16816(float& c0, float& c1, float& c2, float& c3,
                                         uint32_t a0, uint32_t a1, uint32_t a2, uint32_t a3,
                                         uint32_t b0, uint32_t b1) {
    asm volatile(
        "mma.sync.aligned.m16n8k16.row.col.f32.bf16.bf16.f32 "
        "{%0,%1,%2,%3}, {%4,%5,%6,%7}, {%8,%9}, {%0,%1,%2,%3};"
        : "+f"(c0), "+f"(c1), "+f"(c2), "+f"(c3)
        : "r"(a0), "r"(a1), "r"(a2), "r"(a3), "r"(b0), "r"(b1));
}
__device__ __forceinline__ void ldmx4(uint32_t& r0, uint32_t& r1, uint32_t& r2, uint32_t& r3,
                                      uint32_t addr) {
    asm volatile("ldmatrix.sync.aligned.m8n8.x4.shared.b16 {%0,%1,%2,%3}, [%4];"
                 : "=r"(r0), "=r"(r1), "=r"(r2), "=r"(r3) : "r"(addr));
}

// ============================================================================
// Kernel W: build Wih bf16 hi/lo fragments in global (once).
// ============================================================================
__global__ void __launch_bounds__(256) wfrag_kernel(const float* __restrict__ Wih)
{
    const int nt   = blockIdx.x;
    const int tid  = threadIdx.x;
    const int kc   = tid >> 5;
    const int lane = tid & 31;
    const int gid  = lane >> 2, tig = lane & 3;

    const int n = nt * 8 + gid;
    const float* wr = Wih + n * HD + kc * 16;
    const float w0 = wr[2 * tig],     w1 = wr[2 * tig + 1];
    const float w2 = wr[2 * tig + 8], w3 = wr[2 * tig + 9];
    const __nv_bfloat16 h0 = __float2bfloat16(w0), h1 = __float2bfloat16(w1);
    const __nv_bfloat16 h2 = __float2bfloat16(w2), h3 = __float2bfloat16(w3);
    const int idx = (nt * 8 + kc) * 32 + lane;
    g_wfhi[idx] = make_uint2(pkbf(w0, w1), pkbf(w2, w3));
    g_wflo[idx] = make_uint2(
        pkbf(w0 - __bfloat162float(h0), w1 - __bfloat162float(h1)),
        pkbf(w2 - __bfloat162float(h2), w3 - __bfloat162float(h3)));
}

// ============================================================================
// Kernel 0: qpart[b][o] = b0[o] + sum_j (W0a[o,j]+W0c[o,j]) * q[b][j]
// ============================================================================
__global__ void __launch_bounds__(256) qpart_kernel(
    const float* __restrict__ query, const float* __restrict__ W0,
    const float* __restrict__ b0)
{
    __shared__ float sWeff[NA0 * 132];
    __shared__ float sqq[NB * HD];

    const int tid = threadIdx.x;
    const int b0i = blockIdx.x * NB;

    for (int idx = tid; idx < NA0 * HD; idx += 256) {
        const int o = idx >> 7, j = idx & 127;
        sWeff[o * 132 + j] = W0[o * (4 * HD) + j] + W0[o * (4 * HD) + 2 * HD + j];
    }
    for (int idx = tid; idx < NB * HD; idx += 256)
        sqq[idx] = query[b0i * HD + idx];
    __syncthreads();

    const int o  = tid & 63;
    const int bg = tid >> 6;
    unsigned long long acc[4];
    #pragma unroll
    for (int i = 0; i < 4; i++) acc[i] = 0ull;

    #pragma unroll 4
    for (int jc = 0; jc < HD / 4; jc++) {
        const ulonglong2 w = *reinterpret_cast<const ulonglong2*>(&sWeff[o * 132 + jc * 4]);
        #pragma unroll
        for (int i = 0; i < 4; i++) {
            const ulonglong2 x =
                *reinterpret_cast<const ulonglong2*>(&sqq[(bg * 4 + i) * HD + jc * 4]);
            acc[i] = ffma2(w.x, x.x, acc[i]);
            acc[i] = ffma2(w.y, x.y, acc[i]);
        }
    }
    const float bo = b0[o];
    #pragma unroll
    for (int i = 0; i < 4; i++) {
        const float2 p = unpk(acc[i]);
        g_qp[(b0i + bg * 4 + i) * NA0 + o] = p.x + p.y + bo;
    }
}

// ============================================================================
// Kernel 1: DIN attention via tensor cores — 32-row chunks (R12 — validated).
// ============================================================================
#define ACH 32
#define OFFA_BHI 0
#define OFFA_BLO (OFFA_BHI + 8 * 8 * 32 * 8)
#define OFFA_AHI (OFFA_BLO + 8 * 8 * 32 * 8)
#define OFFA_ALO (OFFA_AHI + ACH * APITCH * 2)
#define OFFA_SA0 (OFFA_ALO + ACH * APITCH * 2)
#define OFFA_W1  (OFFA_SA0 + ACH * 68 * 4)
#define OFFA_SQ  (OFFA_W1 + NA1 * 65 * 4)
#define OFFA_QP  (OFFA_SQ + HD * 4)
#define OFFA_WD  (OFFA_QP + NA0 * 4)
#define OFFA_B1  (OFFA_WD + NA1 * 4)
#define ATTN_SMEM (OFFA_B1 + NA1 * 4)

__global__ void __launch_bounds__(256, 3) attn_kernel(
    const float* __restrict__ query, const float* __restrict__ keys,
    const float* __restrict__ W0,
    const float* __restrict__ W1, const float* __restrict__ b1,
    const float* __restrict__ Wd, const float* __restrict__ bd,
    const int* __restrict__ klen)
{
    extern __shared__ char smc[];
    uint2* sBhi = reinterpret_cast<uint2*>(smc + OFFA_BHI);
    uint2* sBlo = reinterpret_cast<uint2*>(smc + OFFA_BLO);
    __nv_bfloat16* sAhi = reinterpret_cast<__nv_bfloat16*>(smc + OFFA_AHI);
    __nv_bfloat16* sAlo = reinterpret_cast<__nv_bfloat16*>(smc + OFFA_ALO);
    float* sa0 = reinterpret_cast<float*>(smc + OFFA_SA0);
    float* sW1 = reinterpret_cast<float*>(smc + OFFA_W1);
    float* sq  = reinterpret_cast<float*>(smc + OFFA_SQ);
    float* sqp = reinterpret_cast<float*>(smc + OFFA_QP);
    float* sWd = reinterpret_cast<float*>(smc + OFFA_WD);
    float* sb1 = reinterpret_cast<float*>(smc + OFFA_B1);

    const int b    = blockIdx.x;
    const int tid  = threadIdx.x;
    const int lenb = klen[b];
    const int lane = tid & 31, warp = tid >> 5;
    const int gid  = lane >> 2, tig = lane & 3;

    if (tid < HD) sq[tid] = query[b * HD + tid];
    if (tid < NA0) sqp[tid] = g_qp[b * NA0 + tid];
    if (tid < NA1) { sWd[tid] = Wd[tid]; sb1[tid] = b1[tid]; }
    for (int i = tid; i < NA1 * NA0; i += 256) {
        const int p = i >> 6, o = i & 63;
        sW1[p * 65 + o] = W1[i];
    }
    const float bd0 = bd[0];
    __syncthreads();

    {
        const int kc = warp;
        #pragma unroll
        for (int nt = 0; nt < 8; nt++) {
            const int n = nt * 8 + gid;
            const float* wr = W0 + n * (4 * HD);
            const int j0 = kc * 16 + 2 * tig;
            const int j2 = j0 + 8;
            const float w0 = wr[HD + j0]     - wr[2 * HD + j0]     + wr[3 * HD + j0]     * sq[j0];
            const float w1 = wr[HD + j0 + 1] - wr[2 * HD + j0 + 1] + wr[3 * HD + j0 + 1] * sq[j0 + 1];
            const float w2 = wr[HD + j2]     - wr[2 * HD + j2]     + wr[3 * HD + j2]     * sq[j2];
            const float w3 = wr[HD + j2 + 1] - wr[2 * HD + j2 + 1] + wr[3 * HD + j2 + 1] * sq[j2 + 1];
            const __nv_bfloat16 h0 = __float2bfloat16(w0), h1 = __float2bfloat16(w1);
            const __nv_bfloat16 h2 = __float2bfloat16(w2), h3 = __float2bfloat16(w3);
            const int idx = (kc * 8 + nt) * 32 + lane;
            sBhi[idx] = make_uint2(pkbf(w0, w1), pkbf(w2, w3));
            sBlo[idx] = make_uint2(
                pkbf(w0 - __bfloat162float(h0), w1 - __bfloat162float(h1)),
                pkbf(w2 - __bfloat162float(h2), w3 - __bfloat162float(h3)));
        }
    }
    __syncthreads();

    const int mt = warp & 1;
    const int nh = warp >> 1;
    const int lm_m = lane >> 3, lm_r = lane & 7;
    const int lm_row = mt * 16 + ((lm_m & 1) ? 8 : 0) + lm_r;
    const int lm_col = (lm_m >> 1) * 8;
    const uint32_t aoff = (uint32_t)((lm_row * APITCH + lm_col) * 2);
    const uint32_t ahi_base = (uint32_t)__cvta_generic_to_shared(sAhi) + aoff;
    const uint32_t alo_base = (uint32_t)__cvta_generic_to_shared(sAlo) + aoff;

    for (int t0c = 0; t0c < TLEN; t0c += ACH) {
        if (t0c >= lenb) {
            for (int i = tid; i < ACH; i += 256) {
                const int tg = t0c + i;
                if (tg < TLEN) g_att[b * TLEN + tg] = 0.0f;
            }
            continue;
        }
        for (int idx = tid; idx < ACH * HD; idx += 256) {
            const int tt = idx >> 7, j = idx & 127;
            const int tg = t0c + tt;
            const float v = (tg < TLEN) ? keys[(b * TLEN + tg) * HD + j] : 0.0f;
            const __nv_bfloat16 h = __float2bfloat16(v);
            sAhi[tt * APITCH + j] = h;
            sAlo[tt * APITCH + j] = __float2bfloat16(v - __bfloat162float(h));
        }
        __syncthreads();

        float c[2][4];
        #pragma unroll
        for (int nt = 0; nt < 2; nt++) {
            const int col = (nh * 2 + nt) * 8 + 2 * tig;
            c[nt][0] = sqp[col]; c[nt][1] = sqp[col + 1];
            c[nt][2] = sqp[col]; c[nt][3] = sqp[col + 1];
        }
        #pragma unroll
        for (int kc = 0; kc < 8; kc++) {
            uint32_t ah0, ah1, ah2, ah3, al0, al1, al2, al3;
            ldmx4(ah0, ah1, ah2, ah3, ahi_base + kc * 32);
            ldmx4(al0, al1, al2, al3, alo_base + kc * 32);
            #pragma unroll
            for (int nt = 0; nt < 2; nt++) {
                const int idx = (kc * 8 + nh * 2 + nt) * 32 + lane;
                const uint2 bh = sBhi[idx];
                const uint2 bl = sBlo[idx];
                mma16816(c[nt][0], c[nt][1], c[nt][2], c[nt][3],
                         ah0, ah1, ah2, ah3, bh.x, bh.y);
                mma16816(c[nt][0], c[nt][1], c[nt][2], c[nt][3],
                         al0, al1, al2, al3, bh.x, bh.y);
                mma16816(c[nt][0], c[nt][1], c[nt][2], c[nt][3],
                         ah0, ah1, ah2, ah3, bl.x, bl.y);
            }
        }
        const int row0 = mt * 16 + gid;
        #pragma unroll
        for (int nt = 0; nt < 2; nt++) {
            const int col = (nh * 2 + nt) * 8 + 2 * tig;
            sa0[row0 * 68 + col]           = sigm(c[nt][0]);
            sa0[row0 * 68 + col + 1]       = sigm(c[nt][1]);
            sa0[(row0 + 8) * 68 + col]     = sigm(c[nt][2]);
            sa0[(row0 + 8) * 68 + col + 1] = sigm(c[nt][3]);
        }
        __syncthreads();

        {
            const int row = tid >> 3, sub = tid & 7;
            const int p0 = sub * 2;
            float s0 = sb1[p0], s1 = sb1[p0 + 1];
            const float* w1r = &sW1[p0 * 65];
            #pragma unroll 8
            for (int o = 0; o < NA0; o++) {
                const float a = sa0[row * 68 + o];
                s0 = fmaf(w1r[o], a, s0);
                s1 = fmaf(w1r[65 + o], a, s1);
            }
            float part = sWd[p0] * sigm(s0) + sWd[p0 + 1] * sigm(s1);
            part += __shfl_xor_sync(0xffffffffu, part, 1);
            part += __shfl_xor_sync(0xffffffffu, part, 2);
            part += __shfl_xor_sync(0xffffffffu, part, 4);
            if (sub == 0) {
                const int tg = t0c + row;
                if (tg < TLEN)
                    g_att[b * TLEN + tg] = (tg < lenb) ? part + bd0 : 0.0f;
            }
        }
        __syncthreads();
    }
}

// ============================================================================
// Kernel 2: gi GEMM via tensor cores (R12 — validated, 4 blocks/SM).
// ============================================================================
__global__ void __launch_bounds__(256, 4) gi_kernel(
    const float* __restrict__ keys, const float* __restrict__ bih,
    const int* __restrict__ klen)
{
    __shared__ __nv_bfloat16 sAhi[64 * APITCH];
    __shared__ __nv_bfloat16 sAlo[64 * APITCH];

    const int b    = blockIdx.z;
    const int t0   = blockIdx.x * 64;
    const int r0   = blockIdx.y * 128;
    const int lenb = klen[b];
    if (t0 >= lenb) return;

    const int tid = threadIdx.x;

    for (int idx = tid; idx < 64 * HD; idx += 256) {
        const int tt = idx >> 7, j = idx & 127;
        const int tg = t0 + tt;
        const float v = (tg < TLEN) ? keys[(b * TLEN + tg) * HD + j] : 0.0f;
        const __nv_bfloat16 h = __float2bfloat16(v);
        sAhi[tt * APITCH + j] = h;
        sAlo[tt * APITCH + j] = __float2bfloat16(v - __bfloat162float(h));
    }
    __syncthreads();

    const int lane = tid & 31, warp = tid >> 5;
    const int gid  = lane >> 2, tig = lane & 3;
    const int mt   = warp & 3;
    const int nh   = warp >> 2;

    const int lm_m = lane >> 3, lm_r = lane & 7;
    const int lm_row = mt * 16 + ((lm_m & 1) ? 8 : 0) + lm_r;
    const int lm_col = (lm_m >> 1) * 8;
    const uint32_t aoff = (uint32_t)((lm_row * APITCH + lm_col) * 2);
    const uint32_t ahi_base = (uint32_t)__cvta_generic_to_shared(sAhi) + aoff;
    const uint32_t alo_base = (uint32_t)__cvta_generic_to_shared(sAlo) + aoff;

    float c[8][4];
    #pragma unroll
    for (int nt = 0; nt < 8; nt++) {
        const int col = r0 + (nh * 8 + nt) * 8 + 2 * tig;
        const float bv0 = bih[col], bv1 = bih[col + 1];
        c[nt][0] = bv0; c[nt][1] = bv1; c[nt][2] = bv0; c[nt][3] = bv1;
    }

    const int ntg0 = (r0 >> 3) + nh * 8;

    #pragma unroll
    for (int kc = 0; kc < 8; kc++) {
        uint32_t ah0, ah1, ah2, ah3, al0, al1, al2, al3;
        ldmx4(ah0, ah1, ah2, ah3, ahi_base + kc * 32);
        ldmx4(al0, al1, al2, al3, alo_base + kc * 32);
        #pragma unroll
        for (int nt = 0; nt < 8; nt++) {
            const int idx = ((ntg0 + nt) * 8 + kc) * 32 + lane;
            const uint2 bh = g_wfhi[idx];
            const uint2 bl = g_wflo[idx];
            mma16816(c[nt][0], c[nt][1], c[nt][2], c[nt][3],
                     ah0, ah1, ah2, ah3, bh.x, bh.y);
            mma16816(c[nt][0], c[nt][1], c[nt][2], c[nt][3],
                     al0, al1, al2, al3, bh.x, bh.y);
            mma16816(c[nt][0], c[nt][1], c[nt][2], c[nt][3],
                     ah0, ah1, ah2, ah3, bl.x, bl.y);
        }
    }

    const int row0 = t0 + mt * 16 + gid;
    const int row1 = row0 + 8;
    #pragma unroll
    for (int nt = 0; nt < 8; nt++) {
        const int col = r0 + (nh * 8 + nt) * 8 + 2 * tig;
        if (row0 < TLEN)
            *reinterpret_cast<float2*>(&g_gi[(b * TLEN + row0) * NR + col]) =
                make_float2(c[nt][0], c[nt][1]);
        if (row1 < TLEN)
            *reinterpret_cast<float2*>(&g_gi[(b * TLEN + row1) * NR + col]) =
                make_float2(c[nt][2], c[nt][3]);
    }
}

// ============================================================================
// Kernel 3: AUGRU scan via tensor cores — 8 warps x N=48 (6 n-tiles/warp).
// Halves per-step A ldmatrix traffic vs 16-warp version; B bytes, tensor
// work, and fragment layout totals unchanged (NFRAG = 8*8*6 = 384).
// ============================================================================
#define NWARP 8
#define NTW   6
#define NFRAG (NWARP * 8 * NTW)
#define OFF_BHI  0
#define OFF_BLO  (NFRAG * 32 * 8)
#define OFF_AHI  (OFF_BLO + NFRAG * 32 * 8)
#define OFF_ALO  (OFF_AHI + NB * APITCH * 2)
#define OFF_SG2  (OFF_ALO + NB * APITCH * 2)
#define OFF_ATT  (OFF_SG2 + NB * SG2P * 4)
#define OFF_LEN  (OFF_ATT + NB * 4)
#define REC_SMEM (OFF_LEN + NB * 4)

__global__ void __launch_bounds__(256, 1) rec_kernel(
    const float* __restrict__ Whh, const float* __restrict__ bhh,
    const int* __restrict__ klen, float* __restrict__ out)
{
    extern __shared__ char smc[];
    uint2* sBhi = reinterpret_cast<uint2*>(smc + OFF_BHI);
    uint2* sBlo = reinterpret_cast<uint2*>(smc + OFF_BLO);
    __nv_bfloat16* sAhi = reinterpret_cast<__nv_bfloat16*>(smc + OFF_AHI);
    __nv_bfloat16* sAlo = reinterpret_cast<__nv_bfloat16*>(smc + OFF_ALO);
    float* sg2  = reinterpret_cast<float*>(smc + OFF_SG2);
    float* satt = reinterpret_cast<float*>(smc + OFF_ATT);
    int*   slen = reinterpret_cast<int*>(smc + OFF_LEN);
    __shared__ int smax;

    const int tid  = threadIdx.x;
    const int lane = tid & 31, warp = tid >> 5;
    const int gid  = lane >> 2, tig = lane & 3;
    const int b0   = blockIdx.x * NB;

    // ---- build B fragments: warp w owns n-slice [w*48, w*48+48) ----
    #pragma unroll
    for (int kc = 0; kc < 8; kc++) {
        #pragma unroll
        for (int nt = 0; nt < NTW; nt++) {
            const int n = warp * 48 + nt * 8 + gid;
            const float* wr = Whh + n * HD + kc * 16;
            const float w0 = wr[2 * tig],     w1 = wr[2 * tig + 1];
            const float w2 = wr[2 * tig + 8], w3 = wr[2 * tig + 9];
            const __nv_bfloat16 h0 = __float2bfloat16(w0), h1 = __float2bfloat16(w1);
            const __nv_bfloat16 h2 = __float2bfloat16(w2), h3 = __float2bfloat16(w3);
            const int idx = ((warp * 8 + kc) * NTW + nt) * 32 + lane;
            sBhi[idx] = make_uint2(pkbf(w0, w1), pkbf(w2, w3));
            sBlo[idx] = make_uint2(
                pkbf(w0 - __bfloat162float(h0), w1 - __bfloat162float(h1)),
                pkbf(w2 - __bfloat162float(h2), w3 - __bfloat162float(h3)));
        }
    }
    for (int i = tid; i < NB * APITCH; i += 256) {
        sAhi[i] = __float2bfloat16(0.0f);
        sAlo[i] = __float2bfloat16(0.0f);
    }
    if (tid < NB) slen[tid] = klen[b0 + tid];
    __syncthreads();
    if (tid == 0) {
        int m = 0;
        #pragma unroll
        for (int b = 0; b < NB; b++) m = max(m, slen[b]);
        smax = m;
    }
    __syncthreads();
    const int tmax = smax;

    const int lm_m = lane >> 3, lm_r = lane & 7;
    const int lm_row = ((lm_m & 1) ? 8 : 0) + lm_r;
    const int lm_col = (lm_m >> 1) * 8;
    const uint32_t aoff = (uint32_t)((lm_row * APITCH + lm_col) * 2);
    const uint32_t ahi_base = (uint32_t)__cvta_generic_to_shared(sAhi) + aoff;
    const uint32_t alo_base = (uint32_t)__cvta_generic_to_shared(sAlo) + aoff;

    float cb0[NTW], cb1[NTW];
    #pragma unroll
    for (int nt = 0; nt < NTW; nt++) {
        cb0[nt] = bhh[warp * 48 + nt * 8 + 2 * tig];
        cb1[nt] = bhh[warp * 48 + nt * 8 + 2 * tig + 1];
    }

    float hreg[8] = {0.0f, 0.0f, 0.0f, 0.0f, 0.0f, 0.0f, 0.0f, 0.0f};

    for (int t = 0; t < tmax; t++) {
        // ---- prefetch gi and att for this step (hidden under MMA) ----
        float pr[8], pz[8], pn[8];
        #pragma unroll
        for (int k = 0; k < 8; k++) {
            const int i = tid + k * 256;
            const int bb = i >> 7, j = i & 127;
            const float* g = &g_gi[((b0 + bb) * TLEN + t) * NR + j];
            pr[k] = g[0];
            pz[k] = g[HD];
            pn[k] = g[2 * HD];
        }
        if (tid < NB) satt[tid] = g_att[(b0 + tid) * TLEN + t];

        // ---- hidden GEMM: sg2 = h @ Whh^T + bhh ----
        float c[NTW][4];
        #pragma unroll
        for (int nt = 0; nt < NTW; nt++) {
            c[nt][0] = cb0[nt]; c[nt][1] = cb1[nt];
            c[nt][2] = cb0[nt]; c[nt][3] = cb1[nt];
        }
        #pragma unroll
        for (int kc = 0; kc < 8; kc++) {
            uint32_t ah0, ah1, ah2, ah3, al0, al1, al2, al3;
            ldmx4(ah0, ah1, ah2, ah3, ahi_base + kc * 32);
            ldmx4(al0, al1, al2, al3, alo_base + kc * 32);
            #pragma unroll
            for (int nt = 0; nt < NTW; nt++) {
                const int idx = ((warp * 8 + kc) * NTW + nt) * 32 + lane;
                const uint2 bh = sBhi[idx];
                const uint2 bl = sBlo[idx];
                mma16816(c[nt][0], c[nt][1], c[nt][2], c[nt][3],
                         ah0, ah1, ah2, ah3, bh.x, bh.y);
                mma16816(c[nt][0], c[nt][1], c[nt][2], c[nt][3],
                         al0, al1, al2, al3, bh.x, bh.y);
                mma16816(c[nt][0], c[nt][1], c[nt][2], c[nt][3],
                         ah0, ah1, ah2, ah3, bl.x, bl.y);
            }
        }
        #pragma unroll
        for (int nt = 0; nt < NTW; nt++) {
            const int colb = warp * 48 + nt * 8 + 2 * tig;
            *reinterpret_cast<float2*>(&sg2[gid * SG2P + colb]) =
                make_float2(c[nt][0], c[nt][1]);
            *reinterpret_cast<float2*>(&sg2[(gid + 8) * SG2P + colb]) =
                make_float2(c[nt][2], c[nt][3]);
        }
        __syncthreads();

        // ---- gated update (freeze past sequence end) ----
        #pragma unroll
        for (int k = 0; k < 8; k++) {
            const int i = tid + k * 256;
            const int bb = i >> 7, j = i & 127;
            if (t < slen[bb]) {
                const float g2r = sg2[bb * SG2P + j];
                const float g2z = sg2[bb * SG2P + HD + j];
                const float g2n = sg2[bb * SG2P + 2 * HD + j];
                const float rr = sigm_t(pr[k] + g2r);
                const float zz = sigm_t(pz[k] + g2z) * satt[bb];
                const float nn = tanh_fast(pn[k] + rr * g2n);
                const float hn = (1.0f - zz) * hreg[k] + zz * nn;
                hreg[k] = hn;
                const __nv_bfloat16 hb = __float2bfloat16(hn);
                sAhi[bb * APITCH + j] = hb;
                sAlo[bb * APITCH + j] = __float2bfloat16(hn - __bfloat162float(hb));
            }
        }
        __syncthreads();
    }

    #pragma unroll
    for (int k = 0; k < 8; k++) {
        const int i = tid + k * 256;
        const int bb = i >> 7, j = i & 127;
        out[(b0 + bb) * HD + j] = (slen[bb] > 0) ? hreg[k] : 0.0f;
    }
}

// ============================================================================
extern "C" void kernel_launch(void* const* d_in, const int* in_sizes, int n_in,
                              void* d_out, int out_size)
{
    const float* query = (const float*)d_in[0];
    const float* keys  = (const float*)d_in[1];
    const float* W0    = (const float*)d_in[2];
    const float* b0    = (const float*)d_in[3];
    const float* W1    = (const float*)d_in[4];
    const float* b1    = (const float*)d_in[5];
    const float* Wd    = (const float*)d_in[6];
    const float* bd    = (const float*)d_in[7];
    const float* Wih   = (const float*)d_in[8];
    const float* Whh   = (const float*)d_in[9];
    const float* bih   = (const float*)d_in[10];
    const float* bhh   = (const float*)d_in[11];
    const int*   klen  = (const int*)d_in[12];
    float* out = (float*)d_out;

    cudaFuncSetAttribute(attn_kernel, cudaFuncAttributeMaxDynamicSharedMemorySize, ATTN_SMEM);
    cudaFuncSetAttribute(rec_kernel,  cudaFuncAttributeMaxDynamicSharedMemorySize, REC_SMEM);

    wfrag_kernel<<<48, 256>>>(Wih);
    qpart_kernel<<<BATCH / NB, 256>>>(query, W0, b0);
    attn_kernel<<<BATCH, 256, ATTN_SMEM>>>(query, keys, W0, W1, b1, Wd, bd, klen);
    gi_kernel<<<dim3(4, 3, BATCH), 256>>>(keys, bih, klen);
    rec_kernel<<<RBLK, 256, REC_SMEM>>>(Whh, bhh, klen, out);
}

// round 14
// speedup vs baseline: 1.0640x; 1.0640x over previous
#include <cuda_runtime.h>
#include <cuda_bf16.h>
#include <cstdint>

#define BATCH 2048
#define TLEN  200
#define HD    128
#define NA0   64
#define NA1   16
#define NB    16
#define RBLK  (BATCH / NB)   // 128 scan blocks
#define NR    384            // 3*HD gate rows
#define SG2P  386            // sg2 pitch (floats), even
#define APITCH 136           // bf16 A pitch: 272B rows -> conflict-free ldmatrix

// ---------------- device scratch (no allocs allowed) ----------------
__device__ float g_att[BATCH * TLEN];            // 1.6 MB attention scores
__device__ float g_qp [BATCH * NA0];             // 0.5 MB qpart
__device__ float g_gi [BATCH * TLEN * NR];       // 629 MB  gi = keys@Wih^T + bih
__device__ uint4 g_wf [48 * 8 * 32];             // Wih fragments hi|lo packed (196KB)

// ---------------- helpers ----------------
__device__ __forceinline__ unsigned long long ffma2(unsigned long long a,
                                                    unsigned long long b,
                                                    unsigned long long c) {
    unsigned long long d;
    asm("fma.rn.f32x2 %0, %1, %2, %3;" : "=l"(d) : "l"(a), "l"(b), "l"(c));
    return d;
}
__device__ __forceinline__ float2 unpk(unsigned long long v) {
    float2 f;
    asm("mov.b64 {%0, %1}, %2;" : "=f"(f.x), "=f"(f.y) : "l"(v));
    return f;
}
__device__ __forceinline__ float sigm(float x) {
    return __fdividef(1.0f, 1.0f + __expf(-x));
}
__device__ __forceinline__ float tanh_fast(float x) {
    float y;
    asm("tanh.approx.f32 %0, %1;" : "=f"(y) : "f"(x));
    return y;
}
__device__ __forceinline__ float sigm_t(float x) {
    return fmaf(0.5f, tanh_fast(0.5f * x), 0.5f);
}
__device__ __forceinline__ uint32_t pkbf(float lo, float hi) {
    __nv_bfloat16 a = __float2bfloat16(lo), b = __float2bfloat16(hi);
    uint16_t ua = *reinterpret_cast<uint16_t*>(&a);
    uint16_t ub = *reinterpret_cast<uint16_t*>(&b);
    return (uint32_t)ua | ((uint32_t)ub << 16);
}
__device__ __forceinline__ void mma16816(float& c0, float& c1, float& c2, float& c3,
                                         uint32_t a0, uint32_t a1, uint32_t a2, uint32_t a3,
                                         uint32_t b0, uint32_t b1) {
    asm volatile(
        "mma.sync.aligned.m16n8k16.row.col.f32.bf16.bf16.f32 "
        "{%0,%1,%2,%3}, {%4,%5,%6,%7}, {%8,%9}, {%0,%1,%2,%3};"
        : "+f"(c0), "+f"(c1), "+f"(c2), "+f"(c3)
        : "r"(a0), "r"(a1), "r"(a2), "r"(a3), "r"(b0), "r"(b1));
}
__device__ __forceinline__ void ldmx4(uint32_t& r0, uint32_t& r1, uint32_t& r2, uint32_t& r3,
                                      uint32_t addr) {
    asm volatile("ldmatrix.sync.aligned.m8n8.x4.shared.b16 {%0,%1,%2,%3}, [%4];"
                 : "=r"(r0), "=r"(r1), "=r"(r2), "=r"(r3) : "r"(addr));
}

// ============================================================================
// Kernel W: build Wih bf16 hi|lo fragments packed as uint4 in global (once).
// ============================================================================
__global__ void __launch_bounds__(256) wfrag_kernel(const float* __restrict__ Wih)
{
    const int nt   = blockIdx.x;
    const int tid  = threadIdx.x;
    const int kc   = tid >> 5;
    const int lane = tid & 31;
    const int gid  = lane >> 2, tig = lane & 3;

    const int n = nt * 8 + gid;
    const float* wr = Wih + n * HD + kc * 16;
    const float w0 = wr[2 * tig],     w1 = wr[2 * tig + 1];
    const float w2 = wr[2 * tig + 8], w3 = wr[2 * tig + 9];
    const __nv_bfloat16 h0 = __float2bfloat16(w0), h1 = __float2bfloat16(w1);
    const __nv_bfloat16 h2 = __float2bfloat16(w2), h3 = __float2bfloat16(w3);
    const int idx = (nt * 8 + kc) * 32 + lane;
    g_wf[idx] = make_uint4(
        pkbf(w0, w1), pkbf(w2, w3),
        pkbf(w0 - __bfloat162float(h0), w1 - __bfloat162float(h1)),
        pkbf(w2 - __bfloat162float(h2), w3 - __bfloat162float(h3)));
}

// ============================================================================
// Kernel 0: qpart[b][o] = b0[o] + sum_j (W0a[o,j]+W0c[o,j]) * q[b][j]
// ============================================================================
__global__ void __launch_bounds__(256) qpart_kernel(
    const float* __restrict__ query, const float* __restrict__ W0,
    const float* __restrict__ b0)
{
    __shared__ float sWeff[NA0 * 132];
    __shared__ float sqq[NB * HD];

    const int tid = threadIdx.x;
    const int b0i = blockIdx.x * NB;

    for (int idx = tid; idx < NA0 * HD; idx += 256) {
        const int o = idx >> 7, j = idx & 127;
        sWeff[o * 132 + j] = W0[o * (4 * HD) + j] + W0[o * (4 * HD) + 2 * HD + j];
    }
    for (int idx = tid; idx < NB * HD; idx += 256)
        sqq[idx] = query[b0i * HD + idx];
    __syncthreads();

    const int o  = tid & 63;
    const int bg = tid >> 6;
    unsigned long long acc[4];
    #pragma unroll
    for (int i = 0; i < 4; i++) acc[i] = 0ull;

    #pragma unroll 4
    for (int jc = 0; jc < HD / 4; jc++) {
        const ulonglong2 w = *reinterpret_cast<const ulonglong2*>(&sWeff[o * 132 + jc * 4]);
        #pragma unroll
        for (int i = 0; i < 4; i++) {
            const ulonglong2 x =
                *reinterpret_cast<const ulonglong2*>(&sqq[(bg * 4 + i) * HD + jc * 4]);
            acc[i] = ffma2(w.x, x.x, acc[i]);
            acc[i] = ffma2(w.y, x.y, acc[i]);
        }
    }
    const float bo = b0[o];
    #pragma unroll
    for (int i = 0; i < 4; i++) {
        const float2 p = unpk(acc[i]);
        g_qp[(b0i + bg * 4 + i) * NA0 + o] = p.x + p.y + bo;
    }
}

// ============================================================================
// Kernel 1: DIN attention via tensor cores — 32-row chunks (R12 — validated).
// ============================================================================
#define ACH 32
#define OFFA_BHI 0
#define OFFA_BLO (OFFA_BHI + 8 * 8 * 32 * 8)
#define OFFA_AHI (OFFA_BLO + 8 * 8 * 32 * 8)
#define OFFA_ALO (OFFA_AHI + ACH * APITCH * 2)
#define OFFA_SA0 (OFFA_ALO + ACH * APITCH * 2)
#define OFFA_W1  (OFFA_SA0 + ACH * 68 * 4)
#define OFFA_SQ  (OFFA_W1 + NA1 * 65 * 4)
#define OFFA_QP  (OFFA_SQ + HD * 4)
#define OFFA_WD  (OFFA_QP + NA0 * 4)
#define OFFA_B1  (OFFA_WD + NA1 * 4)
#define ATTN_SMEM (OFFA_B1 + NA1 * 4)

__global__ void __launch_bounds__(256, 3) attn_kernel(
    const float* __restrict__ query, const float* __restrict__ keys,
    const float* __restrict__ W0,
    const float* __restrict__ W1, const float* __restrict__ b1,
    const float* __restrict__ Wd, const float* __restrict__ bd,
    const int* __restrict__ klen)
{
    extern __shared__ char smc[];
    uint2* sBhi = reinterpret_cast<uint2*>(smc + OFFA_BHI);
    uint2* sBlo = reinterpret_cast<uint2*>(smc + OFFA_BLO);
    __nv_bfloat16* sAhi = reinterpret_cast<__nv_bfloat16*>(smc + OFFA_AHI);
    __nv_bfloat16* sAlo = reinterpret_cast<__nv_bfloat16*>(smc + OFFA_ALO);
    float* sa0 = reinterpret_cast<float*>(smc + OFFA_SA0);
    float* sW1 = reinterpret_cast<float*>(smc + OFFA_W1);
    float* sq  = reinterpret_cast<float*>(smc + OFFA_SQ);
    float* sqp = reinterpret_cast<float*>(smc + OFFA_QP);
    float* sWd = reinterpret_cast<float*>(smc + OFFA_WD);
    float* sb1 = reinterpret_cast<float*>(smc + OFFA_B1);

    const int b    = blockIdx.x;
    const int tid  = threadIdx.x;
    const int lenb = klen[b];
    const int lane = tid & 31, warp = tid >> 5;
    const int gid  = lane >> 2, tig = lane & 3;

    if (tid < HD) sq[tid] = query[b * HD + tid];
    if (tid < NA0) sqp[tid] = g_qp[b * NA0 + tid];
    if (tid < NA1) { sWd[tid] = Wd[tid]; sb1[tid] = b1[tid]; }
    for (int i = tid; i < NA1 * NA0; i += 256) {
        const int p = i >> 6, o = i & 63;
        sW1[p * 65 + o] = W1[i];
    }
    const float bd0 = bd[0];
    __syncthreads();

    {
        const int kc = warp;
        #pragma unroll
        for (int nt = 0; nt < 8; nt++) {
            const int n = nt * 8 + gid;
            const float* wr = W0 + n * (4 * HD);
            const int j0 = kc * 16 + 2 * tig;
            const int j2 = j0 + 8;
            const float w0 = wr[HD + j0]     - wr[2 * HD + j0]     + wr[3 * HD + j0]     * sq[j0];
            const float w1 = wr[HD + j0 + 1] - wr[2 * HD + j0 + 1] + wr[3 * HD + j0 + 1] * sq[j0 + 1];
            const float w2 = wr[HD + j2]     - wr[2 * HD + j2]     + wr[3 * HD + j2]     * sq[j2];
            const float w3 = wr[HD + j2 + 1] - wr[2 * HD + j2 + 1] + wr[3 * HD + j2 + 1] * sq[j2 + 1];
            const __nv_bfloat16 h0 = __float2bfloat16(w0), h1 = __float2bfloat16(w1);
            const __nv_bfloat16 h2 = __float2bfloat16(w2), h3 = __float2bfloat16(w3);
            const int idx = (kc * 8 + nt) * 32 + lane;
            sBhi[idx] = make_uint2(pkbf(w0, w1), pkbf(w2, w3));
            sBlo[idx] = make_uint2(
                pkbf(w0 - __bfloat162float(h0), w1 - __bfloat162float(h1)),
                pkbf(w2 - __bfloat162float(h2), w3 - __bfloat162float(h3)));
        }
    }
    __syncthreads();

    const int mt = warp & 1;
    const int nh = warp >> 1;
    const int lm_m = lane >> 3, lm_r = lane & 7;
    const int lm_row = mt * 16 + ((lm_m & 1) ? 8 : 0) + lm_r;
    const int lm_col = (lm_m >> 1) * 8;
    const uint32_t aoff = (uint32_t)((lm_row * APITCH + lm_col) * 2);
    const uint32_t ahi_base = (uint32_t)__cvta_generic_to_shared(sAhi) + aoff;
    const uint32_t alo_base = (uint32_t)__cvta_generic_to_shared(sAlo) + aoff;

    for (int t0c = 0; t0c < TLEN; t0c += ACH) {
        if (t0c >= lenb) {
            for (int i = tid; i < ACH; i += 256) {
                const int tg = t0c + i;
                if (tg < TLEN) g_att[b * TLEN + tg] = 0.0f;
            }
            continue;
        }
        for (int idx = tid; idx < ACH * HD; idx += 256) {
            const int tt = idx >> 7, j = idx & 127;
            const int tg = t0c + tt;
            const float v = (tg < TLEN) ? keys[(b * TLEN + tg) * HD + j] : 0.0f;
            const __nv_bfloat16 h = __float2bfloat16(v);
            sAhi[tt * APITCH + j] = h;
            sAlo[tt * APITCH + j] = __float2bfloat16(v - __bfloat162float(h));
        }
        __syncthreads();

        float c[2][4];
        #pragma unroll
        for (int nt = 0; nt < 2; nt++) {
            const int col = (nh * 2 + nt) * 8 + 2 * tig;
            c[nt][0] = sqp[col]; c[nt][1] = sqp[col + 1];
            c[nt][2] = sqp[col]; c[nt][3] = sqp[col + 1];
        }
        #pragma unroll
        for (int kc = 0; kc < 8; kc++) {
            uint32_t ah0, ah1, ah2, ah3, al0, al1, al2, al3;
            ldmx4(ah0, ah1, ah2, ah3, ahi_base + kc * 32);
            ldmx4(al0, al1, al2, al3, alo_base + kc * 32);
            #pragma unroll
            for (int nt = 0; nt < 2; nt++) {
                const int idx = (kc * 8 + nh * 2 + nt) * 32 + lane;
                const uint2 bh = sBhi[idx];
                const uint2 bl = sBlo[idx];
                mma16816(c[nt][0], c[nt][1], c[nt][2], c[nt][3],
                         ah0, ah1, ah2, ah3, bh.x, bh.y);
                mma16816(c[nt][0], c[nt][1], c[nt][2], c[nt][3],
                         al0, al1, al2, al3, bh.x, bh.y);
                mma16816(c[nt][0], c[nt][1], c[nt][2], c[nt][3],
                         ah0, ah1, ah2, ah3, bl.x, bl.y);
            }
        }
        const int row0 = mt * 16 + gid;
        #pragma unroll
        for (int nt = 0; nt < 2; nt++) {
            const int col = (nh * 2 + nt) * 8 + 2 * tig;
            sa0[row0 * 68 + col]           = sigm(c[nt][0]);
            sa0[row0 * 68 + col + 1]       = sigm(c[nt][1]);
            sa0[(row0 + 8) * 68 + col]     = sigm(c[nt][2]);
            sa0[(row0 + 8) * 68 + col + 1] = sigm(c[nt][3]);
        }
        __syncthreads();

        {
            const int row = tid >> 3, sub = tid & 7;
            const int p0 = sub * 2;
            float s0 = sb1[p0], s1 = sb1[p0 + 1];
            const float* w1r = &sW1[p0 * 65];
            #pragma unroll 8
            for (int o = 0; o < NA0; o++) {
                const float a = sa0[row * 68 + o];
                s0 = fmaf(w1r[o], a, s0);
                s1 = fmaf(w1r[65 + o], a, s1);
            }
            float part = sWd[p0] * sigm(s0) + sWd[p0 + 1] * sigm(s1);
            part += __shfl_xor_sync(0xffffffffu, part, 1);
            part += __shfl_xor_sync(0xffffffffu, part, 2);
            part += __shfl_xor_sync(0xffffffffu, part, 4);
            if (sub == 0) {
                const int tg = t0c + row;
                if (tg < TLEN)
                    g_att[b * TLEN + tg] = (tg < lenb) ? part + bd0 : 0.0f;
            }
        }
        __syncthreads();
    }
}

// ============================================================================
// Kernel 2: gi GEMM via tensor cores — packed uint4 fragments (one LDG.128
// per (nt,kc) instead of two LDG.64).  Otherwise R12 (4 blocks/SM).
// ============================================================================
__global__ void __launch_bounds__(256, 4) gi_kernel(
    const float* __restrict__ keys, const float* __restrict__ bih,
    const int* __restrict__ klen)
{
    __shared__ __nv_bfloat16 sAhi[64 * APITCH];
    __shared__ __nv_bfloat16 sAlo[64 * APITCH];

    const int b    = blockIdx.z;
    const int t0   = blockIdx.x * 64;
    const int r0   = blockIdx.y * 128;
    const int lenb = klen[b];
    if (t0 >= lenb) return;

    const int tid = threadIdx.x;

    for (int idx = tid; idx < 64 * HD; idx += 256) {
        const int tt = idx >> 7, j = idx & 127;
        const int tg = t0 + tt;
        const float v = (tg < TLEN) ? keys[(b * TLEN + tg) * HD + j] : 0.0f;
        const __nv_bfloat16 h = __float2bfloat16(v);
        sAhi[tt * APITCH + j] = h;
        sAlo[tt * APITCH + j] = __float2bfloat16(v - __bfloat162float(h));
    }
    __syncthreads();

    const int lane = tid & 31, warp = tid >> 5;
    const int gid  = lane >> 2, tig = lane & 3;
    const int mt   = warp & 3;
    const int nh   = warp >> 2;

    const int lm_m = lane >> 3, lm_r = lane & 7;
    const int lm_row = mt * 16 + ((lm_m & 1) ? 8 : 0) + lm_r;
    const int lm_col = (lm_m >> 1) * 8;
    const uint32_t aoff = (uint32_t)((lm_row * APITCH + lm_col) * 2);
    const uint32_t ahi_base = (uint32_t)__cvta_generic_to_shared(sAhi) + aoff;
    const uint32_t alo_base = (uint32_t)__cvta_generic_to_shared(sAlo) + aoff;

    float c[8][4];
    #pragma unroll
    for (int nt = 0; nt < 8; nt++) {
        const int col = r0 + (nh * 8 + nt) * 8 + 2 * tig;
        const float bv0 = bih[col], bv1 = bih[col + 1];
        c[nt][0] = bv0; c[nt][1] = bv1; c[nt][2] = bv0; c[nt][3] = bv1;
    }

    const int ntg0 = (r0 >> 3) + nh * 8;

    #pragma unroll
    for (int kc = 0; kc < 8; kc++) {
        uint32_t ah0, ah1, ah2, ah3, al0, al1, al2, al3;
        ldmx4(ah0, ah1, ah2, ah3, ahi_base + kc * 32);
        ldmx4(al0, al1, al2, al3, alo_base + kc * 32);
        #pragma unroll
        for (int nt = 0; nt < 8; nt++) {
            const int idx = ((ntg0 + nt) * 8 + kc) * 32 + lane;
            const uint4 w = g_wf[idx];                 // hi.x hi.y lo.x lo.y
            mma16816(c[nt][0], c[nt][1], c[nt][2], c[nt][3],
                     ah0, ah1, ah2, ah3, w.x, w.y);
            mma16816(c[nt][0], c[nt][1], c[nt][2], c[nt][3],
                     al0, al1, al2, al3, w.x, w.y);
            mma16816(c[nt][0], c[nt][1], c[nt][2], c[nt][3],
                     ah0, ah1, ah2, ah3, w.z, w.w);
        }
    }

    const int row0 = t0 + mt * 16 + gid;
    const int row1 = row0 + 8;
    #pragma unroll
    for (int nt = 0; nt < 8; nt++) {
        const int col = r0 + (nh * 8 + nt) * 8 + 2 * tig;
        if (row0 < TLEN)
            *reinterpret_cast<float2*>(&g_gi[(b * TLEN + row0) * NR + col]) =
                make_float2(c[nt][0], c[nt][1]);
        if (row1 < TLEN)
            *reinterpret_cast<float2*>(&g_gi[(b * TLEN + row1) * NR + col]) =
                make_float2(c[nt][2], c[nt][3]);
    }
}

// ============================================================================
// Kernel 3: AUGRU scan via tensor cores (R8/R12 16-warp version — validated).
// ============================================================================
#define NWARP 16
#define NTW   3
#define NFRAG (NWARP * 8 * NTW)
#define OFF_BHI  0
#define OFF_BLO  (NFRAG * 32 * 8)
#define OFF_AHI  (OFF_BLO + NFRAG * 32 * 8)
#define OFF_ALO  (OFF_AHI + NB * APITCH * 2)
#define OFF_SG2  (OFF_ALO + NB * APITCH * 2)
#define OFF_ATT  (OFF_SG2 + NB * SG2P * 4)
#define OFF_LEN  (OFF_ATT + NB * 4)
#define REC_SMEM (OFF_LEN + NB * 4)

__global__ void __launch_bounds__(512, 1) rec_kernel(
    const float* __restrict__ Whh, const float* __restrict__ bhh,
    const int* __restrict__ klen, float* __restrict__ out)
{
    extern __shared__ char smc[];
    uint2* sBhi = reinterpret_cast<uint2*>(smc + OFF_BHI);
    uint2* sBlo = reinterpret_cast<uint2*>(smc + OFF_BLO);
    __nv_bfloat16* sAhi = reinterpret_cast<__nv_bfloat16*>(smc + OFF_AHI);
    __nv_bfloat16* sAlo = reinterpret_cast<__nv_bfloat16*>(smc + OFF_ALO);
    float* sg2  = reinterpret_cast<float*>(smc + OFF_SG2);
    float* satt = reinterpret_cast<float*>(smc + OFF_ATT);
    int*   slen = reinterpret_cast<int*>(smc + OFF_LEN);
    __shared__ int smax;

    const int tid  = threadIdx.x;
    const int lane = tid & 31, warp = tid >> 5;
    const int gid  = lane >> 2, tig = lane & 3;
    const int b0   = blockIdx.x * NB;

    #pragma unroll
    for (int kc = 0; kc < 8; kc++) {
        #pragma unroll
        for (int nt = 0; nt < NTW; nt++) {
            const int n = warp * 24 + nt * 8 + gid;
            const float* wr = Whh + n * HD + kc * 16;
            const float w0 = wr[2 * tig],     w1 = wr[2 * tig + 1];
            const float w2 = wr[2 * tig + 8], w3 = wr[2 * tig + 9];
            const __nv_bfloat16 h0 = __float2bfloat16(w0), h1 = __float2bfloat16(w1);
            const __nv_bfloat16 h2 = __float2bfloat16(w2), h3 = __float2bfloat16(w3);
            const int idx = ((warp * 8 + kc) * NTW + nt) * 32 + lane;
            sBhi[idx] = make_uint2(pkbf(w0, w1), pkbf(w2, w3));
            sBlo[idx] = make_uint2(
                pkbf(w0 - __bfloat162float(h0), w1 - __bfloat162float(h1)),
                pkbf(w2 - __bfloat162float(h2), w3 - __bfloat162float(h3)));
        }
    }
    for (int i = tid; i < NB * APITCH; i += 512) {
        sAhi[i] = __float2bfloat16(0.0f);
        sAlo[i] = __float2bfloat16(0.0f);
    }
    if (tid < NB) slen[tid] = klen[b0 + tid];
    __syncthreads();
    if (tid == 0) {
        int m = 0;
        #pragma unroll
        for (int b = 0; b < NB; b++) m = max(m, slen[b]);
        smax = m;
    }
    __syncthreads();
    const int tmax = smax;

    const int lm_m = lane >> 3, lm_r = lane & 7;
    const int lm_row = ((lm_m & 1) ? 8 : 0) + lm_r;
    const int lm_col = (lm_m >> 1) * 8;
    const uint32_t aoff = (uint32_t)((lm_row * APITCH + lm_col) * 2);
    const uint32_t ahi_base = (uint32_t)__cvta_generic_to_shared(sAhi) + aoff;
    const uint32_t alo_base = (uint32_t)__cvta_generic_to_shared(sAlo) + aoff;

    float cb0[NTW], cb1[NTW];
    #pragma unroll
    for (int nt = 0; nt < NTW; nt++) {
        cb0[nt] = bhh[warp * 24 + nt * 8 + 2 * tig];
        cb1[nt] = bhh[warp * 24 + nt * 8 + 2 * tig + 1];
    }

    float hreg[4] = {0.0f, 0.0f, 0.0f, 0.0f};

    for (int t = 0; t < tmax; t++) {
        float pr[4], pz[4], pn[4];
        #pragma unroll
        for (int k = 0; k < 4; k++) {
            const int i = tid + k * 512;
            const int bb = i >> 7, j = i & 127;
            const float* g = &g_gi[((b0 + bb) * TLEN + t) * NR + j];
            pr[k] = g[0];
            pz[k] = g[HD];
            pn[k] = g[2 * HD];
        }
        if (tid < NB) satt[tid] = g_att[(b0 + tid) * TLEN + t];

        float c[NTW][4];
        #pragma unroll
        for (int nt = 0; nt < NTW; nt++) {
            c[nt][0] = cb0[nt]; c[nt][1] = cb1[nt];
            c[nt][2] = cb0[nt]; c[nt][3] = cb1[nt];
        }
        #pragma unroll
        for (int kc = 0; kc < 8; kc++) {
            uint32_t ah0, ah1, ah2, ah3, al0, al1, al2, al3;
            ldmx4(ah0, ah1, ah2, ah3, ahi_base + kc * 32);
            ldmx4(al0, al1, al2, al3, alo_base + kc * 32);
            #pragma unroll
            for (int nt = 0; nt < NTW; nt++) {
                const int idx = ((warp * 8 + kc) * NTW + nt) * 32 + lane;
                const uint2 bh = sBhi[idx];
                const uint2 bl = sBlo[idx];
                mma16816(c[nt][0], c[nt][1], c[nt][2], c[nt][3],
                         ah0, ah1, ah2, ah3, bh.x, bh.y);
                mma16816(c[nt][0], c[nt][1], c[nt][2], c[nt][3],
                         al0, al1, al2, al3, bh.x, bh.y);
                mma16816(c[nt][0], c[nt][1], c[nt][2], c[nt][3],
                         ah0, ah1, ah2, ah3, bl.x, bl.y);
            }
        }
        #pragma unroll
        for (int nt = 0; nt < NTW; nt++) {
            const int colb = warp * 24 + nt * 8 + 2 * tig;
            *reinterpret_cast<float2*>(&sg2[gid * SG2P + colb]) =
                make_float2(c[nt][0], c[nt][1]);
            *reinterpret_cast<float2*>(&sg2[(gid + 8) * SG2P + colb]) =
                make_float2(c[nt][2], c[nt][3]);
        }
        __syncthreads();

        #pragma unroll
        for (int k = 0; k < 4; k++) {
            const int i = tid + k * 512;
            const int bb = i >> 7, j = i & 127;
            if (t < slen[bb]) {
                const float g2r = sg2[bb * SG2P + j];
                const float g2z = sg2[bb * SG2P + HD + j];
                const float g2n = sg2[bb * SG2P + 2 * HD + j];
                const float rr = sigm_t(pr[k] + g2r);
                const float zz = sigm_t(pz[k] + g2z) * satt[bb];
                const float nn = tanh_fast(pn[k] + rr * g2n);
                const float hn = (1.0f - zz) * hreg[k] + zz * nn;
                hreg[k] = hn;
                const __nv_bfloat16 hb = __float2bfloat16(hn);
                sAhi[bb * APITCH + j] = hb;
                sAlo[bb * APITCH + j] = __float2bfloat16(hn - __bfloat162float(hb));
            }
        }
        __syncthreads();
    }

    #pragma unroll
    for (int k = 0; k < 4; k++) {
        const int i = tid + k * 512;
        const int bb = i >> 7, j = i & 127;
        out[(b0 + bb) * HD + j] = (slen[bb] > 0) ? hreg[k] : 0.0f;
    }
}

// ============================================================================
extern "C" void kernel_launch(void* const* d_in, const int* in_sizes, int n_in,
                              void* d_out, int out_size)
{
    const float* query = (const float*)d_in[0];
    const float* keys  = (const float*)d_in[1];
    const float* W0    = (const float*)d_in[2];
    const float* b0    = (const float*)d_in[3];
    const float* W1    = (const float*)d_in[4];
    const float* b1    = (const float*)d_in[5];
    const float* Wd    = (const float*)d_in[6];
    const float* bd    = (const float*)d_in[7];
    const float* Wih   = (const float*)d_in[8];
    const float* Whh   = (const float*)d_in[9];
    const float* bih   = (const float*)d_in[10];
    const float* bhh   = (const float*)d_in[11];
    const int*   klen  = (const int*)d_in[12];
    float* out = (float*)d_out;

    cudaFuncSetAttribute(attn_kernel, cudaFuncAttributeMaxDynamicSharedMemorySize, ATTN_SMEM);
    cudaFuncSetAttribute(rec_kernel,  cudaFuncAttributeMaxDynamicSharedMemorySize, REC_SMEM);

    wfrag_kernel<<<48, 256>>>(Wih);
    qpart_kernel<<<BATCH / NB, 256>>>(query, W0, b0);
    attn_kernel<<<BATCH, 256, ATTN_SMEM>>>(query, keys, W0, W1, b1, Wd, bd, klen);
    gi_kernel<<<dim3(4, 3, BATCH), 256>>>(keys, bih, klen);
    rec_kernel<<<RBLK, 512, REC_SMEM>>>(Whh, bhh, klen, out);
}

// round 15
// speedup vs baseline: 1.0869x; 1.0215x over previous
#include <cuda_runtime.h>
#include <cuda_bf16.h>
#include <cstdint>

#define BATCH 2048
#define TLEN  200
#define HD    128
#define NA0   64
#define NA1   16
#define NB    16
#define RBLK  (BATCH / NB)   // 128 scan blocks
#define NR    384            // 3*HD gate rows
#define SG2P  386            // sg2 pitch (floats), even
#define APITCH 136           // bf16 A pitch: 272B rows -> conflict-free ldmatrix

// ---------------- device scratch (no allocs allowed) ----------------
__device__ float g_att[BATCH * TLEN];            // 1.6 MB attention scores
__device__ float g_qp [BATCH * NA0];             // 0.5 MB qpart
__device__ float g_gi [BATCH * TLEN * NR];       // 629 MB  gi = keys@Wih^T + bih
__device__ uint4 g_wf [48 * 8 * 32];             // Wih fragments hi|lo packed (196KB)

// ---------------- helpers ----------------
__device__ __forceinline__ unsigned long long ffma2(unsigned long long a,
                                                    unsigned long long b,
                                                    unsigned long long c) {
    unsigned long long d;
    asm("fma.rn.f32x2 %0, %1, %2, %3;" : "=l"(d) : "l"(a), "l"(b), "l"(c));
    return d;
}
__device__ __forceinline__ float2 unpk(unsigned long long v) {
    float2 f;
    asm("mov.b64 {%0, %1}, %2;" : "=f"(f.x), "=f"(f.y) : "l"(v));
    return f;
}
__device__ __forceinline__ float sigm(float x) {
    return __fdividef(1.0f, 1.0f + __expf(-x));
}
__device__ __forceinline__ float tanh_fast(float x) {
    float y;
    asm("tanh.approx.f32 %0, %1;" : "=f"(y) : "f"(x));
    return y;
}
__device__ __forceinline__ float sigm_t(float x) {
    return fmaf(0.5f, tanh_fast(0.5f * x), 0.5f);
}
__device__ __forceinline__ uint32_t pkbf(float lo, float hi) {
    __nv_bfloat16 a = __float2bfloat16(lo), b = __float2bfloat16(hi);
    uint16_t ua = *reinterpret_cast<uint16_t*>(&a);
    uint16_t ub = *reinterpret_cast<uint16_t*>(&b);
    return (uint32_t)ua | ((uint32_t)ub << 16);
}
__device__ __forceinline__ void mma16816(float& c0, float& c1, float& c2, float& c3,
                                         uint32_t a0, uint32_t a1, uint32_t a2, uint32_t a3,
                                         uint32_t b0, uint32_t b1) {
    asm volatile(
        "mma.sync.aligned.m16n8k16.row.col.f32.bf16.bf16.f32 "
        "{%0,%1,%2,%3}, {%4,%5,%6,%7}, {%8,%9}, {%0,%1,%2,%3};"
        : "+f"(c0), "+f"(c1), "+f"(c2), "+f"(c3)
        : "r"(a0), "r"(a1), "r"(a2), "r"(a3), "r"(b0), "r"(b1));
}
__device__ __forceinline__ void ldmx4(uint32_t& r0, uint32_t& r1, uint32_t& r2, uint32_t& r3,
                                      uint32_t addr) {
    asm volatile("ldmatrix.sync.aligned.m8n8.x4.shared.b16 {%0,%1,%2,%3}, [%4];"
                 : "=r"(r0), "=r"(r1), "=r"(r2), "=r"(r3) : "r"(addr));
}

// ============================================================================
// Kernel W: build Wih bf16 hi|lo fragments packed as uint4 in global (once).
// ============================================================================
__global__ void __launch_bounds__(256) wfrag_kernel(const float* __restrict__ Wih)
{
    const int nt   = blockIdx.x;
    const int tid  = threadIdx.x;
    const int kc   = tid >> 5;
    const int lane = tid & 31;
    const int gid  = lane >> 2, tig = lane & 3;

    const int n = nt * 8 + gid;
    const float* wr = Wih + n * HD + kc * 16;
    const float w0 = wr[2 * tig],     w1 = wr[2 * tig + 1];
    const float w2 = wr[2 * tig + 8], w3 = wr[2 * tig + 9];
    const __nv_bfloat16 h0 = __float2bfloat16(w0), h1 = __float2bfloat16(w1);
    const __nv_bfloat16 h2 = __float2bfloat16(w2), h3 = __float2bfloat16(w3);
    const int idx = (nt * 8 + kc) * 32 + lane;
    g_wf[idx] = make_uint4(
        pkbf(w0, w1), pkbf(w2, w3),
        pkbf(w0 - __bfloat162float(h0), w1 - __bfloat162float(h1)),
        pkbf(w2 - __bfloat162float(h2), w3 - __bfloat162float(h3)));
}

// ============================================================================
// Kernel 0: qpart[b][o] = b0[o] + sum_j (W0a[o,j]+W0c[o,j]) * q[b][j]
// ============================================================================
__global__ void __launch_bounds__(256) qpart_kernel(
    const float* __restrict__ query, const float* __restrict__ W0,
    const float* __restrict__ b0)
{
    __shared__ float sWeff[NA0 * 132];
    __shared__ float sqq[NB * HD];

    const int tid = threadIdx.x;
    const int b0i = blockIdx.x * NB;

    for (int idx = tid; idx < NA0 * HD; idx += 256) {
        const int o = idx >> 7, j = idx & 127;
        sWeff[o * 132 + j] = W0[o * (4 * HD) + j] + W0[o * (4 * HD) + 2 * HD + j];
    }
    for (int idx = tid; idx < NB * HD; idx += 256)
        sqq[idx] = query[b0i * HD + idx];
    __syncthreads();

    const int o  = tid & 63;
    const int bg = tid >> 6;
    unsigned long long acc[4];
    #pragma unroll
    for (int i = 0; i < 4; i++) acc[i] = 0ull;

    #pragma unroll 4
    for (int jc = 0; jc < HD / 4; jc++) {
        const ulonglong2 w = *reinterpret_cast<const ulonglong2*>(&sWeff[o * 132 + jc * 4]);
        #pragma unroll
        for (int i = 0; i < 4; i++) {
            const ulonglong2 x =
                *reinterpret_cast<const ulonglong2*>(&sqq[(bg * 4 + i) * HD + jc * 4]);
            acc[i] = ffma2(w.x, x.x, acc[i]);
            acc[i] = ffma2(w.y, x.y, acc[i]);
        }
    }
    const float bo = b0[o];
    #pragma unroll
    for (int i = 0; i < 4; i++) {
        const float2 p = unpk(acc[i]);
        g_qp[(b0i + bg * 4 + i) * NA0 + o] = p.x + p.y + bo;
    }
}

// ============================================================================
// Kernel 1: DIN attention via tensor cores — 32-row chunks (R12 — validated).
// ============================================================================
#define ACH 32
#define OFFA_BHI 0
#define OFFA_BLO (OFFA_BHI + 8 * 8 * 32 * 8)
#define OFFA_AHI (OFFA_BLO + 8 * 8 * 32 * 8)
#define OFFA_ALO (OFFA_AHI + ACH * APITCH * 2)
#define OFFA_SA0 (OFFA_ALO + ACH * APITCH * 2)
#define OFFA_W1  (OFFA_SA0 + ACH * 68 * 4)
#define OFFA_SQ  (OFFA_W1 + NA1 * 65 * 4)
#define OFFA_QP  (OFFA_SQ + HD * 4)
#define OFFA_WD  (OFFA_QP + NA0 * 4)
#define OFFA_B1  (OFFA_WD + NA1 * 4)
#define ATTN_SMEM (OFFA_B1 + NA1 * 4)

__global__ void __launch_bounds__(256, 3) attn_kernel(
    const float* __restrict__ query, const float* __restrict__ keys,
    const float* __restrict__ W0,
    const float* __restrict__ W1, const float* __restrict__ b1,
    const float* __restrict__ Wd, const float* __restrict__ bd,
    const int* __restrict__ klen)
{
    extern __shared__ char smc[];
    uint2* sBhi = reinterpret_cast<uint2*>(smc + OFFA_BHI);
    uint2* sBlo = reinterpret_cast<uint2*>(smc + OFFA_BLO);
    __nv_bfloat16* sAhi = reinterpret_cast<__nv_bfloat16*>(smc + OFFA_AHI);
    __nv_bfloat16* sAlo = reinterpret_cast<__nv_bfloat16*>(smc + OFFA_ALO);
    float* sa0 = reinterpret_cast<float*>(smc + OFFA_SA0);
    float* sW1 = reinterpret_cast<float*>(smc + OFFA_W1);
    float* sq  = reinterpret_cast<float*>(smc + OFFA_SQ);
    float* sqp = reinterpret_cast<float*>(smc + OFFA_QP);
    float* sWd = reinterpret_cast<float*>(smc + OFFA_WD);
    float* sb1 = reinterpret_cast<float*>(smc + OFFA_B1);

    const int b    = blockIdx.x;
    const int tid  = threadIdx.x;
    const int lenb = klen[b];
    const int lane = tid & 31, warp = tid >> 5;
    const int gid  = lane >> 2, tig = lane & 3;

    if (tid < HD) sq[tid] = query[b * HD + tid];
    if (tid < NA0) sqp[tid] = g_qp[b * NA0 + tid];
    if (tid < NA1) { sWd[tid] = Wd[tid]; sb1[tid] = b1[tid]; }
    for (int i = tid; i < NA1 * NA0; i += 256) {
        const int p = i >> 6, o = i & 63;
        sW1[p * 65 + o] = W1[i];
    }
    const float bd0 = bd[0];
    __syncthreads();

    {
        const int kc = warp;
        #pragma unroll
        for (int nt = 0; nt < 8; nt++) {
            const int n = nt * 8 + gid;
            const float* wr = W0 + n * (4 * HD);
            const int j0 = kc * 16 + 2 * tig;
            const int j2 = j0 + 8;
            const float w0 = wr[HD + j0]     - wr[2 * HD + j0]     + wr[3 * HD + j0]     * sq[j0];
            const float w1 = wr[HD + j0 + 1] - wr[2 * HD + j0 + 1] + wr[3 * HD + j0 + 1] * sq[j0 + 1];
            const float w2 = wr[HD + j2]     - wr[2 * HD + j2]     + wr[3 * HD + j2]     * sq[j2];
            const float w3 = wr[HD + j2 + 1] - wr[2 * HD + j2 + 1] + wr[3 * HD + j2 + 1] * sq[j2 + 1];
            const __nv_bfloat16 h0 = __float2bfloat16(w0), h1 = __float2bfloat16(w1);
            const __nv_bfloat16 h2 = __float2bfloat16(w2), h3 = __float2bfloat16(w3);
            const int idx = (kc * 8 + nt) * 32 + lane;
            sBhi[idx] = make_uint2(pkbf(w0, w1), pkbf(w2, w3));
            sBlo[idx] = make_uint2(
                pkbf(w0 - __bfloat162float(h0), w1 - __bfloat162float(h1)),
                pkbf(w2 - __bfloat162float(h2), w3 - __bfloat162float(h3)));
        }
    }
    __syncthreads();

    const int mt = warp & 1;
    const int nh = warp >> 1;
    const int lm_m = lane >> 3, lm_r = lane & 7;
    const int lm_row = mt * 16 + ((lm_m & 1) ? 8 : 0) + lm_r;
    const int lm_col = (lm_m >> 1) * 8;
    const uint32_t aoff = (uint32_t)((lm_row * APITCH + lm_col) * 2);
    const uint32_t ahi_base = (uint32_t)__cvta_generic_to_shared(sAhi) + aoff;
    const uint32_t alo_base = (uint32_t)__cvta_generic_to_shared(sAlo) + aoff;

    for (int t0c = 0; t0c < TLEN; t0c += ACH) {
        if (t0c >= lenb) {
            for (int i = tid; i < ACH; i += 256) {
                const int tg = t0c + i;
                if (tg < TLEN) g_att[b * TLEN + tg] = 0.0f;
            }
            continue;
        }
        for (int idx = tid; idx < ACH * HD; idx += 256) {
            const int tt = idx >> 7, j = idx & 127;
            const int tg = t0c + tt;
            const float v = (tg < TLEN) ? keys[(b * TLEN + tg) * HD + j] : 0.0f;
            const __nv_bfloat16 h = __float2bfloat16(v);
            sAhi[tt * APITCH + j] = h;
            sAlo[tt * APITCH + j] = __float2bfloat16(v - __bfloat162float(h));
        }
        __syncthreads();

        float c[2][4];
        #pragma unroll
        for (int nt = 0; nt < 2; nt++) {
            const int col = (nh * 2 + nt) * 8 + 2 * tig;
            c[nt][0] = sqp[col]; c[nt][1] = sqp[col + 1];
            c[nt][2] = sqp[col]; c[nt][3] = sqp[col + 1];
        }
        #pragma unroll
        for (int kc = 0; kc < 8; kc++) {
            uint32_t ah0, ah1, ah2, ah3, al0, al1, al2, al3;
            ldmx4(ah0, ah1, ah2, ah3, ahi_base + kc * 32);
            ldmx4(al0, al1, al2, al3, alo_base + kc * 32);
            #pragma unroll
            for (int nt = 0; nt < 2; nt++) {
                const int idx = (kc * 8 + nh * 2 + nt) * 32 + lane;
                const uint2 bh = sBhi[idx];
                const uint2 bl = sBlo[idx];
                mma16816(c[nt][0], c[nt][1], c[nt][2], c[nt][3],
                         ah0, ah1, ah2, ah3, bh.x, bh.y);
                mma16816(c[nt][0], c[nt][1], c[nt][2], c[nt][3],
                         al0, al1, al2, al3, bh.x, bh.y);
                mma16816(c[nt][0], c[nt][1], c[nt][2], c[nt][3],
                         ah0, ah1, ah2, ah3, bl.x, bl.y);
            }
        }
        const int row0 = mt * 16 + gid;
        #pragma unroll
        for (int nt = 0; nt < 2; nt++) {
            const int col = (nh * 2 + nt) * 8 + 2 * tig;
            sa0[row0 * 68 + col]           = sigm(c[nt][0]);
            sa0[row0 * 68 + col + 1]       = sigm(c[nt][1]);
            sa0[(row0 + 8) * 68 + col]     = sigm(c[nt][2]);
            sa0[(row0 + 8) * 68 + col + 1] = sigm(c[nt][3]);
        }
        __syncthreads();

        {
            const int row = tid >> 3, sub = tid & 7;
            const int p0 = sub * 2;
            float s0 = sb1[p0], s1 = sb1[p0 + 1];
            const float* w1r = &sW1[p0 * 65];
            #pragma unroll 8
            for (int o = 0; o < NA0; o++) {
                const float a = sa0[row * 68 + o];
                s0 = fmaf(w1r[o], a, s0);
                s1 = fmaf(w1r[65 + o], a, s1);
            }
            float part = sWd[p0] * sigm(s0) + sWd[p0 + 1] * sigm(s1);
            part += __shfl_xor_sync(0xffffffffu, part, 1);
            part += __shfl_xor_sync(0xffffffffu, part, 2);
            part += __shfl_xor_sync(0xffffffffu, part, 4);
            if (sub == 0) {
                const int tg = t0c + row;
                if (tg < TLEN)
                    g_att[b * TLEN + tg] = (tg < lenb) ? part + bd0 : 0.0f;
            }
        }
        __syncthreads();
    }
}

// ============================================================================
// Kernel 2: gi GEMM via tensor cores — warp tile 2 m-tiles x 4 n-tiles.
// 8 warps = 2 m-pairs x 4 n-groups.  B fragments reused across both m-tiles:
// per-warp L1 wavefronts drop 320 -> 256 (B 256->128, A 64->128).
// ============================================================================
__global__ void __launch_bounds__(256, 3) gi_kernel(
    const float* __restrict__ keys, const float* __restrict__ bih,
    const int* __restrict__ klen)
{
    __shared__ __nv_bfloat16 sAhi[64 * APITCH];
    __shared__ __nv_bfloat16 sAlo[64 * APITCH];

    const int b    = blockIdx.z;
    const int t0   = blockIdx.x * 64;
    const int r0   = blockIdx.y * 128;
    const int lenb = klen[b];
    if (t0 >= lenb) return;

    const int tid = threadIdx.x;

    for (int idx = tid; idx < 64 * HD; idx += 256) {
        const int tt = idx >> 7, j = idx & 127;
        const int tg = t0 + tt;
        const float v = (tg < TLEN) ? keys[(b * TLEN + tg) * HD + j] : 0.0f;
        const __nv_bfloat16 h = __float2bfloat16(v);
        sAhi[tt * APITCH + j] = h;
        sAlo[tt * APITCH + j] = __float2bfloat16(v - __bfloat162float(h));
    }
    __syncthreads();

    const int lane = tid & 31, warp = tid >> 5;
    const int gid  = lane >> 2, tig = lane & 3;
    const int mp   = warp & 1;     // m-pair: m-tiles mp*2, mp*2+1 (rows mp*32..+32)
    const int nh   = warp >> 1;    // n-group: 4 n-tiles at nh*4

    const int lm_m = lane >> 3, lm_r = lane & 7;
    const int lm_rowb = ((lm_m & 1) ? 8 : 0) + lm_r;
    const int lm_col  = (lm_m >> 1) * 8;
    // two A bases, one per m-tile of this pair (16 rows apart)
    uint32_t ahi_base[2], alo_base[2];
    #pragma unroll
    for (int mi = 0; mi < 2; mi++) {
        const int row = (mp * 2 + mi) * 16 + lm_rowb;
        const uint32_t aoff = (uint32_t)((row * APITCH + lm_col) * 2);
        ahi_base[mi] = (uint32_t)__cvta_generic_to_shared(sAhi) + aoff;
        alo_base[mi] = (uint32_t)__cvta_generic_to_shared(sAlo) + aoff;
    }

    float c[2][4][4];
    #pragma unroll
    for (int nt = 0; nt < 4; nt++) {
        const int col = r0 + (nh * 4 + nt) * 8 + 2 * tig;
        const float bv0 = bih[col], bv1 = bih[col + 1];
        #pragma unroll
        for (int mi = 0; mi < 2; mi++) {
            c[mi][nt][0] = bv0; c[mi][nt][1] = bv1;
            c[mi][nt][2] = bv0; c[mi][nt][3] = bv1;
        }
    }

    const int ntg0 = (r0 >> 3) + nh * 4;

    #pragma unroll
    for (int kc = 0; kc < 8; kc++) {
        uint32_t ah[2][4], al[2][4];
        #pragma unroll
        for (int mi = 0; mi < 2; mi++) {
            ldmx4(ah[mi][0], ah[mi][1], ah[mi][2], ah[mi][3], ahi_base[mi] + kc * 32);
            ldmx4(al[mi][0], al[mi][1], al[mi][2], al[mi][3], alo_base[mi] + kc * 32);
        }
        #pragma unroll
        for (int nt = 0; nt < 4; nt++) {
            const int idx = ((ntg0 + nt) * 8 + kc) * 32 + lane;
            const uint4 w = g_wf[idx];                 // hi.x hi.y lo.x lo.y
            #pragma unroll
            for (int mi = 0; mi < 2; mi++) {
                mma16816(c[mi][nt][0], c[mi][nt][1], c[mi][nt][2], c[mi][nt][3],
                         ah[mi][0], ah[mi][1], ah[mi][2], ah[mi][3], w.x, w.y);
                mma16816(c[mi][nt][0], c[mi][nt][1], c[mi][nt][2], c[mi][nt][3],
                         al[mi][0], al[mi][1], al[mi][2], al[mi][3], w.x, w.y);
                mma16816(c[mi][nt][0], c[mi][nt][1], c[mi][nt][2], c[mi][nt][3],
                         ah[mi][0], ah[mi][1], ah[mi][2], ah[mi][3], w.z, w.w);
            }
        }
    }

    #pragma unroll
    for (int mi = 0; mi < 2; mi++) {
        const int row0 = t0 + (mp * 2 + mi) * 16 + gid;
        const int row1 = row0 + 8;
        #pragma unroll
        for (int nt = 0; nt < 4; nt++) {
            const int col = r0 + (nh * 4 + nt) * 8 + 2 * tig;
            if (row0 < TLEN)
                *reinterpret_cast<float2*>(&g_gi[(b * TLEN + row0) * NR + col]) =
                    make_float2(c[mi][nt][0], c[mi][nt][1]);
            if (row1 < TLEN)
                *reinterpret_cast<float2*>(&g_gi[(b * TLEN + row1) * NR + col]) =
                    make_float2(c[mi][nt][2], c[mi][nt][3]);
        }
    }
}

// ============================================================================
// Kernel 3: AUGRU scan via tensor cores (R8/R12 16-warp version — validated).
// ============================================================================
#define NWARP 16
#define NTW   3
#define NFRAG (NWARP * 8 * NTW)
#define OFF_BHI  0
#define OFF_BLO  (NFRAG * 32 * 8)
#define OFF_AHI  (OFF_BLO + NFRAG * 32 * 8)
#define OFF_ALO  (OFF_AHI + NB * APITCH * 2)
#define OFF_SG2  (OFF_ALO + NB * APITCH * 2)
#define OFF_ATT  (OFF_SG2 + NB * SG2P * 4)
#define OFF_LEN  (OFF_ATT + NB * 4)
#define REC_SMEM (OFF_LEN + NB * 4)

__global__ void __launch_bounds__(512, 1) rec_kernel(
    const float* __restrict__ Whh, const float* __restrict__ bhh,
    const int* __restrict__ klen, float* __restrict__ out)
{
    extern __shared__ char smc[];
    uint2* sBhi = reinterpret_cast<uint2*>(smc + OFF_BHI);
    uint2* sBlo = reinterpret_cast<uint2*>(smc + OFF_BLO);
    __nv_bfloat16* sAhi = reinterpret_cast<__nv_bfloat16*>(smc + OFF_AHI);
    __nv_bfloat16* sAlo = reinterpret_cast<__nv_bfloat16*>(smc + OFF_ALO);
    float* sg2  = reinterpret_cast<float*>(smc + OFF_SG2);
    float* satt = reinterpret_cast<float*>(smc + OFF_ATT);
    int*   slen = reinterpret_cast<int*>(smc + OFF_LEN);
    __shared__ int smax;

    const int tid  = threadIdx.x;
    const int lane = tid & 31, warp = tid >> 5;
    const int gid  = lane >> 2, tig = lane & 3;
    const int b0   = blockIdx.x * NB;

    #pragma unroll
    for (int kc = 0; kc < 8; kc++) {
        #pragma unroll
        for (int nt = 0; nt < NTW; nt++) {
            const int n = warp * 24 + nt * 8 + gid;
            const float* wr = Whh + n * HD + kc * 16;
            const float w0 = wr[2 * tig],     w1 = wr[2 * tig + 1];
            const float w2 = wr[2 * tig + 8], w3 = wr[2 * tig + 9];
            const __nv_bfloat16 h0 = __float2bfloat16(w0), h1 = __float2bfloat16(w1);
            const __nv_bfloat16 h2 = __float2bfloat16(w2), h3 = __float2bfloat16(w3);
            const int idx = ((warp * 8 + kc) * NTW + nt) * 32 + lane;
            sBhi[idx] = make_uint2(pkbf(w0, w1), pkbf(w2, w3));
            sBlo[idx] = make_uint2(
                pkbf(w0 - __bfloat162float(h0), w1 - __bfloat162float(h1)),
                pkbf(w2 - __bfloat162float(h2), w3 - __bfloat162float(h3)));
        }
    }
    for (int i = tid; i < NB * APITCH; i += 512) {
        sAhi[i] = __float2bfloat16(0.0f);
        sAlo[i] = __float2bfloat16(0.0f);
    }
    if (tid < NB) slen[tid] = klen[b0 + tid];
    __syncthreads();
    if (tid == 0) {
        int m = 0;
        #pragma unroll
        for (int b = 0; b < NB; b++) m = max(m, slen[b]);
        smax = m;
    }
    __syncthreads();
    const int tmax = smax;

    const int lm_m = lane >> 3, lm_r = lane & 7;
    const int lm_row = ((lm_m & 1) ? 8 : 0) + lm_r;
    const int lm_col = (lm_m >> 1) * 8;
    const uint32_t aoff = (uint32_t)((lm_row * APITCH + lm_col) * 2);
    const uint32_t ahi_base = (uint32_t)__cvta_generic_to_shared(sAhi) + aoff;
    const uint32_t alo_base = (uint32_t)__cvta_generic_to_shared(sAlo) + aoff;

    float cb0[NTW], cb1[NTW];
    #pragma unroll
    for (int nt = 0; nt < NTW; nt++) {
        cb0[nt] = bhh[warp * 24 + nt * 8 + 2 * tig];
        cb1[nt] = bhh[warp * 24 + nt * 8 + 2 * tig + 1];
    }

    float hreg[4] = {0.0f, 0.0f, 0.0f, 0.0f};

    for (int t = 0; t < tmax; t++) {
        float pr[4], pz[4], pn[4];
        #pragma unroll
        for (int k = 0; k < 4; k++) {
            const int i = tid + k * 512;
            const int bb = i >> 7, j = i & 127;
            const float* g = &g_gi[((b0 + bb) * TLEN + t) * NR + j];
            pr[k] = g[0];
            pz[k] = g[HD];
            pn[k] = g[2 * HD];
        }
        if (tid < NB) satt[tid] = g_att[(b0 + tid) * TLEN + t];

        float c[NTW][4];
        #pragma unroll
        for (int nt = 0; nt < NTW; nt++) {
            c[nt][0] = cb0[nt]; c[nt][1] = cb1[nt];
            c[nt][2] = cb0[nt]; c[nt][3] = cb1[nt];
        }
        #pragma unroll
        for (int kc = 0; kc < 8; kc++) {
            uint32_t ah0, ah1, ah2, ah3, al0, al1, al2, al3;
            ldmx4(ah0, ah1, ah2, ah3, ahi_base + kc * 32);
            ldmx4(al0, al1, al2, al3, alo_base + kc * 32);
            #pragma unroll
            for (int nt = 0; nt < NTW; nt++) {
                const int idx = ((warp * 8 + kc) * NTW + nt) * 32 + lane;
                const uint2 bh = sBhi[idx];
                const uint2 bl = sBlo[idx];
                mma16816(c[nt][0], c[nt][1], c[nt][2], c[nt][3],
                         ah0, ah1, ah2, ah3, bh.x, bh.y);
                mma16816(c[nt][0], c[nt][1], c[nt][2], c[nt][3],
                         al0, al1, al2, al3, bh.x, bh.y);
                mma16816(c[nt][0], c[nt][1], c[nt][2], c[nt][3],
                         ah0, ah1, ah2, ah3, bl.x, bl.y);
            }
        }
        #pragma unroll
        for (int nt = 0; nt < NTW; nt++) {
            const int colb = warp * 24 + nt * 8 + 2 * tig;
            *reinterpret_cast<float2*>(&sg2[gid * SG2P + colb]) =
                make_float2(c[nt][0], c[nt][1]);
            *reinterpret_cast<float2*>(&sg2[(gid + 8) * SG2P + colb]) =
                make_float2(c[nt][2], c[nt][3]);
        }
        __syncthreads();

        #pragma unroll
        for (int k = 0; k < 4; k++) {
            const int i = tid + k * 512;
            const int bb = i >> 7, j = i & 127;
            if (t < slen[bb]) {
                const float g2r = sg2[bb * SG2P + j];
                const float g2z = sg2[bb * SG2P + HD + j];
                const float g2n = sg2[bb * SG2P + 2 * HD + j];
                const float rr = sigm_t(pr[k] + g2r);
                const float zz = sigm_t(pz[k] + g2z) * satt[bb];
                const float nn = tanh_fast(pn[k] + rr * g2n);
                const float hn = (1.0f - zz) * hreg[k] + zz * nn;
                hreg[k] = hn;
                const __nv_bfloat16 hb = __float2bfloat16(hn);
                sAhi[bb * APITCH + j] = hb;
                sAlo[bb * APITCH + j] = __float2bfloat16(hn - __bfloat162float(hb));
            }
        }
        __syncthreads();
    }

    #pragma unroll
    for (int k = 0; k < 4; k++) {
        const int i = tid + k * 512;
        const int bb = i >> 7, j = i & 127;
        out[(b0 + bb) * HD + j] = (slen[bb] > 0) ? hreg[k] : 0.0f;
    }
}

// ============================================================================
extern "C" void kernel_launch(void* const* d_in, const int* in_sizes, int n_in,
                              void* d_out, int out_size)
{
    const float* query = (const float*)d_in[0];
    const float* keys  = (const float*)d_in[1];
    const float* W0    = (const float*)d_in[2];
    const float* b0    = (const float*)d_in[3];
    const float* W1    = (const float*)d_in[4];
    const float* b1    = (const float*)d_in[5];
    const float* Wd    = (const float*)d_in[6];
    const float* bd    = (const float*)d_in[7];
    const float* Wih   = (const float*)d_in[8];
    const float* Whh   = (const float*)d_in[9];
    const float* bih   = (const float*)d_in[10];
    const float* bhh   = (const float*)d_in[11];
    const int*   klen  = (const int*)d_in[12];
    float* out = (float*)d_out;

    cudaFuncSetAttribute(attn_kernel, cudaFuncAttributeMaxDynamicSharedMemorySize, ATTN_SMEM);
    cudaFuncSetAttribute(rec_kernel,  cudaFuncAttributeMaxDynamicSharedMemorySize, REC_SMEM);

    wfrag_kernel<<<48, 256>>>(Wih);
    qpart_kernel<<<BATCH / NB, 256>>>(query, W0, b0);
    attn_kernel<<<BATCH, 256, ATTN_SMEM>>>(query, keys, W0, W1, b1, Wd, bd, klen);
    gi_kernel<<<dim3(4, 3, BATCH), 256>>>(keys, bih, klen);
    rec_kernel<<<RBLK, 512, REC_SMEM>>>(Whh, bhh, klen, out);
}